// round 3
// baseline (speedup 1.0000x reference)
#include <cuda_runtime.h>
#include <cstdint>
#include <math_constants.h>

// Problem constants
constexpr int Bb  = 2;
constexpr int Cc  = 128;
constexpr int Nn  = 50000;
constexpr int Mm  = Bb * Nn;
constexpr int Hh  = 2;
constexpr int FHh = 64;
constexpr int OUT = Hh * FHh; // 128
constexpr int Ee  = 800000;

constexpr float NEG_SLOPE_GAT = 0.2f;
constexpr float NEG_SLOPE_ACT = 0.01f;
constexpr float LN_EPS = 1e-5f;
constexpr float SOFTMAX_EPS = 1e-16f;

// Scratch (device globals: allocation-free)
__device__ float  g_hl[(size_t)Mm * OUT];
__device__ float  g_hr[(size_t)Mm * OUT];
__device__ float2 g_logits[(size_t)Ee];      // (head0, head1) per edge
__device__ int    g_deg[Mm];
__device__ int    g_cnt[Mm];
__device__ int    g_rowptr[Mm + 1];
__device__ int    g_csr_src[Ee];
__device__ float2 g_csr_logit[Ee];

__device__ __forceinline__ uint32_t f2tf32(float f) {
    uint32_t u;
    asm("cvt.rna.tf32.f32 %0, %1;" : "=r"(u) : "f"(f));
    return u;
}

// ---- K0: zero counters ----
__global__ void k_init() {
    int i = blockIdx.x * blockDim.x + threadIdx.x;
    if (i < Mm) { g_deg[i] = 0; g_cnt[i] = 0; }
}

// ---- K1: fused transpose + dual GEMM via tf32 mma.sync ----
constexpr int BM = 128, BN = 128, BK = 32;

__global__ void __launch_bounds__(256, 2)
k_gemm_tc(const float* __restrict__ x,
          const float* __restrict__ Wl, const float* __restrict__ bl,
          const float* __restrict__ Wr, const float* __restrict__ br) {
    const float* W    = blockIdx.y ? Wr : Wl;
    const float* bias = blockIdx.y ? br : bl;
    float* h          = blockIdx.y ? g_hr : g_hl;

    __shared__ uint32_t xs[BM][BK + 4];
    __shared__ uint32_t ws[BK][BN + 12];

    int tid  = threadIdx.x;
    int lane = tid & 31;
    int wid  = tid >> 5;
    int wm   = wid & 3;
    int wn   = wid >> 2;
    int lrow = lane >> 2;
    int lcol = lane & 3;

    int m0 = blockIdx.x * BM;

    int ml   = tid & 127;
    int kc   = tid >> 7;
    int m_l  = m0 + ml;
    bool rowok = m_l < Mm;
    int bb = rowok ? (m_l / Nn) : 0;
    int nn = rowok ? (m_l % Nn) : 0;
    const float* xrow = x + (size_t)bb * Cc * Nn + nn;

    float acc[2][8][4];
    #pragma unroll
    for (int mt = 0; mt < 2; mt++)
        #pragma unroll
        for (int nt = 0; nt < 8; nt++)
            #pragma unroll
            for (int q = 0; q < 4; q++) acc[mt][nt][q] = 0.f;

    for (int k0 = 0; k0 < Cc; k0 += BK) {
        #pragma unroll
        for (int k = kc; k < BK; k += 2) {
            float v = rowok ? xrow[(size_t)(k0 + k) * Nn] : 0.f;
            xs[ml][k] = f2tf32(v);
        }
        #pragma unroll
        for (int k = kc; k < BK; k += 2) {
            ws[k][ml] = f2tf32(W[(size_t)(k0 + k) * OUT + ml]);
        }
        __syncthreads();

        #pragma unroll
        for (int kk = 0; kk < 4; kk++) {
            int kb = kk * 8;
            uint32_t af[2][4];
            #pragma unroll
            for (int mt = 0; mt < 2; mt++) {
                int r = wm * 32 + mt * 16 + lrow;
                af[mt][0] = xs[r][kb + lcol];
                af[mt][1] = xs[r + 8][kb + lcol];
                af[mt][2] = xs[r][kb + lcol + 4];
                af[mt][3] = xs[r + 8][kb + lcol + 4];
            }
            #pragma unroll
            for (int nt = 0; nt < 8; nt++) {
                int cn = wn * 64 + nt * 8 + lrow;
                uint32_t b0 = ws[kb + lcol][cn];
                uint32_t b1 = ws[kb + lcol + 4][cn];
                #pragma unroll
                for (int mt = 0; mt < 2; mt++) {
                    asm volatile(
                        "mma.sync.aligned.m16n8k8.row.col.f32.tf32.tf32.f32 "
                        "{%0,%1,%2,%3}, {%4,%5,%6,%7}, {%8,%9}, {%0,%1,%2,%3};\n"
                        : "+f"(acc[mt][nt][0]), "+f"(acc[mt][nt][1]),
                          "+f"(acc[mt][nt][2]), "+f"(acc[mt][nt][3])
                        : "r"(af[mt][0]), "r"(af[mt][1]), "r"(af[mt][2]), "r"(af[mt][3]),
                          "r"(b0), "r"(b1));
                }
            }
        }
        __syncthreads();
    }

    #pragma unroll
    for (int mt = 0; mt < 2; mt++) {
        #pragma unroll
        for (int nt = 0; nt < 8; nt++) {
            int row = m0 + wm * 32 + mt * 16 + lrow;
            int col = wn * 64 + nt * 8 + lcol * 2;
            float bcol0 = bias[col], bcol1 = bias[col + 1];
            if (row < Mm) {
                float2 v = {acc[mt][nt][0] + bcol0, acc[mt][nt][1] + bcol1};
                *(float2*)&h[(size_t)row * OUT + col] = v;
            }
            if (row + 8 < Mm) {
                float2 v = {acc[mt][nt][2] + bcol0, acc[mt][nt][3] + bcol1};
                *(float2*)&h[(size_t)(row + 8) * OUT + col] = v;
            }
        }
    }
}

// ---- K2: edge scoring + degree count. One warp per edge. ----
__global__ void k_score(const int* __restrict__ ei, const float* __restrict__ att) {
    int gid  = blockIdx.x * blockDim.x + threadIdx.x;
    int e    = gid >> 5;
    int lane = threadIdx.x & 31;
    if (e >= Ee) return;
    int s = ei[e], d = ei[Ee + e];
    const float4 l4 = *(const float4*)(g_hl + (size_t)s * OUT + lane * 4);
    const float4 r4 = *(const float4*)(g_hr + (size_t)d * OUT + lane * 4);
    const float4 a4 = *(const float4*)(att + lane * 4);
    float vx = l4.x + r4.x, vy = l4.y + r4.y, vz = l4.z + r4.z, vw = l4.w + r4.w;
    vx = vx > 0.f ? vx : NEG_SLOPE_GAT * vx;
    vy = vy > 0.f ? vy : NEG_SLOPE_GAT * vy;
    vz = vz > 0.f ? vz : NEG_SLOPE_GAT * vz;
    vw = vw > 0.f ? vw : NEG_SLOPE_GAT * vw;
    float p = vx * a4.x + vy * a4.y + vz * a4.z + vw * a4.w;
    #pragma unroll
    for (int off = 8; off > 0; off >>= 1)
        p += __shfl_xor_sync(0xFFFFFFFFu, p, off);
    float other = __shfl_sync(0xFFFFFFFFu, p, 16);
    if (lane == 0) {
        g_logits[e] = make_float2(p, other);
        atomicAdd(&g_deg[d], 1);
    }
}

// ---- K3: single-block exclusive scan of degrees -> rowptr ----
__global__ void k_scan() {
    constexpr int T  = 1024;
    constexpr int CH = (Mm + T - 1) / T;
    __shared__ int ssum[T];
    int t = threadIdx.x;
    int base = t * CH;
    int local = 0;
    #pragma unroll 4
    for (int i = 0; i < CH; i++) {
        int idx = base + i;
        if (idx < Mm) local += g_deg[idx];
    }
    ssum[t] = local;
    __syncthreads();
    for (int off = 1; off < T; off <<= 1) {
        int v = (t >= off) ? ssum[t - off] : 0;
        __syncthreads();
        ssum[t] += v;
        __syncthreads();
    }
    int run = (t == 0) ? 0 : ssum[t - 1];
    for (int i = 0; i < CH; i++) {
        int idx = base + i;
        if (idx < Mm) { g_rowptr[idx] = run; run += g_deg[idx]; }
    }
    if (t == T - 1) g_rowptr[Mm] = run;
}

// ---- K4: scatter edges into CSR order ----
__global__ void k_scatter(const int* __restrict__ ei) {
    int e = blockIdx.x * blockDim.x + threadIdx.x;
    if (e >= Ee) return;
    int d = ei[Ee + e];
    int pos = g_rowptr[d] + atomicAdd(&g_cnt[d], 1);
    g_csr_src[pos]   = ei[e];
    g_csr_logit[pos] = g_logits[e];
}

// ---- K5: gather-aggregate + softmax + bias + LayerNorm + LeakyReLU. Warp per dst. ----
__global__ void __launch_bounds__(256)
k_gather(float* __restrict__ out, const float* __restrict__ bias,
         const float* __restrict__ gamma, const float* __restrict__ beta) {
    int gid  = blockIdx.x * blockDim.x + threadIdx.x;
    int m    = gid >> 5;
    int lane = threadIdx.x & 31;
    if (m >= Mm) return;
    int start = g_rowptr[m];
    int deg   = g_rowptr[m + 1] - start;

    // segment max per head
    float mx0 = -CUDART_INF_F, mx1 = -CUDART_INF_F;
    for (int j = lane; j < deg; j += 32) {
        float2 l = g_csr_logit[start + j];
        mx0 = fmaxf(mx0, l.x);
        mx1 = fmaxf(mx1, l.y);
    }
    #pragma unroll
    for (int off = 16; off > 0; off >>= 1) {
        mx0 = fmaxf(mx0, __shfl_xor_sync(0xFFFFFFFFu, mx0, off));
        mx1 = fmaxf(mx1, __shfl_xor_sync(0xFFFFFFFFu, mx1, off));
    }

    int   hh = lane >> 4;              // head owning this lane's 4 features
    float acc0 = 0.f, acc1 = 0.f, acc2 = 0.f, acc3 = 0.f;
    float den0 = 0.f, den1 = 0.f;

    for (int j = 0; j < deg; j++) {
        float2 l = g_csr_logit[start + j];   // broadcast load
        int    s = g_csr_src[start + j];     // broadcast load
        float w0 = __expf(l.x - mx0);
        float w1 = __expf(l.y - mx1);
        den0 += w0; den1 += w1;
        float w = hh ? w1 : w0;
        const float4 v = *(const float4*)(g_hl + (size_t)s * OUT + lane * 4);
        acc0 += w * v.x; acc1 += w * v.y; acc2 += w * v.z; acc3 += w * v.w;
    }

    float inv_d = 1.f / ((hh ? den1 : den0) + SOFTMAX_EPS);
    const float4 b4 = *(const float4*)(bias + lane * 4);
    float v0 = acc0 * inv_d + b4.x;
    float v1 = acc1 * inv_d + b4.y;
    float v2 = acc2 * inv_d + b4.z;
    float v3 = acc3 * inv_d + b4.w;

    float s  = v0 + v1 + v2 + v3;
    float s2 = v0 * v0 + v1 * v1 + v2 * v2 + v3 * v3;
    #pragma unroll
    for (int off = 16; off > 0; off >>= 1) {
        s  += __shfl_xor_sync(0xFFFFFFFFu, s,  off);
        s2 += __shfl_xor_sync(0xFFFFFFFFu, s2, off);
    }
    float mu  = s * (1.f / OUT);
    float var = s2 * (1.f / OUT) - mu * mu;
    float inv = rsqrtf(var + LN_EPS);

    const float4 g4 = *(const float4*)(gamma + lane * 4);
    const float4 t4 = *(const float4*)(beta + lane * 4);
    float4 y;
    y.x = (v0 - mu) * inv * g4.x + t4.x;
    y.y = (v1 - mu) * inv * g4.y + t4.y;
    y.z = (v2 - mu) * inv * g4.z + t4.z;
    y.w = (v3 - mu) * inv * g4.w + t4.w;
    y.x = y.x > 0.f ? y.x : NEG_SLOPE_ACT * y.x;
    y.y = y.y > 0.f ? y.y : NEG_SLOPE_ACT * y.y;
    y.z = y.z > 0.f ? y.z : NEG_SLOPE_ACT * y.z;
    y.w = y.w > 0.f ? y.w : NEG_SLOPE_ACT * y.w;
    *(float4*)(out + (size_t)m * OUT + lane * 4) = y;
}

extern "C" void kernel_launch(void* const* d_in, const int* in_sizes, int n_in,
                              void* d_out, int out_size) {
    const float* x        = (const float*)d_in[0];
    const int*   ei       = (const int*)  d_in[1];
    const float* Wl       = (const float*)d_in[2];
    const float* bl       = (const float*)d_in[3];
    const float* Wr       = (const float*)d_in[4];
    const float* br       = (const float*)d_in[5];
    const float* att      = (const float*)d_in[6];
    const float* bias_gat = (const float*)d_in[7];
    const float* gamma    = (const float*)d_in[8];
    const float* beta     = (const float*)d_in[9];
    float* out = (float*)d_out;

    (void)in_sizes; (void)n_in; (void)out_size;

    k_init<<<(Mm + 255) / 256, 256>>>();

    dim3 ggrid((Mm + BM - 1) / BM, 2);
    k_gemm_tc<<<ggrid, 256>>>(x, Wl, bl, Wr, br);

    k_score<<<(Ee * 32 + 255) / 256, 256>>>(ei, att);
    k_scan<<<1, 1024>>>();
    k_scatter<<<(Ee + 255) / 256, 256>>>(ei);
    k_gather<<<(Mm * 32 + 255) / 256, 256>>>(out, bias_gat, gamma, beta);
}

// round 4
// speedup vs baseline: 1.3018x; 1.3018x over previous
#include <cuda_runtime.h>
#include <cstdint>
#include <math_constants.h>

// Problem constants
constexpr int Bb  = 2;
constexpr int Cc  = 128;
constexpr int Nn  = 50000;
constexpr int Mm  = Bb * Nn;
constexpr int Hh  = 2;
constexpr int FHh = 64;
constexpr int OUT = Hh * FHh; // 128
constexpr int Ee  = 800000;

constexpr float NEG_SLOPE_GAT = 0.2f;
constexpr float NEG_SLOPE_ACT = 0.01f;
constexpr float LN_EPS = 1e-5f;
constexpr float SOFTMAX_EPS = 1e-16f;

// Parallel scan config
constexpr int SCAN_T  = 1024;
constexpr int NSB     = (Mm + SCAN_T - 1) / SCAN_T;  // 98 blocks

// Scratch (device globals: allocation-free)
__device__ float  g_hl[(size_t)Mm * OUT];
__device__ float  g_hr[(size_t)Mm * OUT];
__device__ float2 g_logits[(size_t)Ee];
__device__ int    g_deg[Mm];
__device__ int    g_cnt[Mm];
__device__ int    g_rowptr[Mm + 1];
__device__ int    g_csr_src[Ee];
__device__ float2 g_csr_logit[Ee];
__device__ int    g_blocksum[NSB];
__device__ int    g_blockoff[NSB];

__device__ __forceinline__ uint32_t f2tf32(float f) {
    uint32_t u;
    asm("cvt.rna.tf32.f32 %0, %1;" : "=r"(u) : "f"(f));
    return u;
}

// ---- K0: zero counters ----
__global__ void k_init() {
    int i = blockIdx.x * blockDim.x + threadIdx.x;
    if (i < Mm) { g_deg[i] = 0; g_cnt[i] = 0; }
}

// ---- K1: fused transpose + dual GEMM via tf32 mma.sync ----
constexpr int BM = 128, BN = 128, BK = 32;

__global__ void __launch_bounds__(256, 2)
k_gemm_tc(const float* __restrict__ x,
          const float* __restrict__ Wl, const float* __restrict__ bl,
          const float* __restrict__ Wr, const float* __restrict__ br) {
    const float* W    = blockIdx.y ? Wr : Wl;
    const float* bias = blockIdx.y ? br : bl;
    float* h          = blockIdx.y ? g_hr : g_hl;

    __shared__ uint32_t xs[BM][BK + 4];
    __shared__ uint32_t ws[BK][BN + 12];

    int tid  = threadIdx.x;
    int lane = tid & 31;
    int wid  = tid >> 5;
    int wm   = wid & 3;
    int wn   = wid >> 2;
    int lrow = lane >> 2;
    int lcol = lane & 3;

    int m0 = blockIdx.x * BM;

    int ml   = tid & 127;
    int kc   = tid >> 7;
    int m_l  = m0 + ml;
    bool rowok = m_l < Mm;
    int bb = rowok ? (m_l / Nn) : 0;
    int nn = rowok ? (m_l % Nn) : 0;
    const float* xrow = x + (size_t)bb * Cc * Nn + nn;

    float acc[2][8][4];
    #pragma unroll
    for (int mt = 0; mt < 2; mt++)
        #pragma unroll
        for (int nt = 0; nt < 8; nt++)
            #pragma unroll
            for (int q = 0; q < 4; q++) acc[mt][nt][q] = 0.f;

    for (int k0 = 0; k0 < Cc; k0 += BK) {
        #pragma unroll
        for (int k = kc; k < BK; k += 2) {
            float v = rowok ? xrow[(size_t)(k0 + k) * Nn] : 0.f;
            xs[ml][k] = f2tf32(v);
        }
        #pragma unroll
        for (int k = kc; k < BK; k += 2) {
            ws[k][ml] = f2tf32(W[(size_t)(k0 + k) * OUT + ml]);
        }
        __syncthreads();

        #pragma unroll
        for (int kk = 0; kk < 4; kk++) {
            int kb = kk * 8;
            uint32_t af[2][4];
            #pragma unroll
            for (int mt = 0; mt < 2; mt++) {
                int r = wm * 32 + mt * 16 + lrow;
                af[mt][0] = xs[r][kb + lcol];
                af[mt][1] = xs[r + 8][kb + lcol];
                af[mt][2] = xs[r][kb + lcol + 4];
                af[mt][3] = xs[r + 8][kb + lcol + 4];
            }
            #pragma unroll
            for (int nt = 0; nt < 8; nt++) {
                int cn = wn * 64 + nt * 8 + lrow;
                uint32_t b0 = ws[kb + lcol][cn];
                uint32_t b1 = ws[kb + lcol + 4][cn];
                #pragma unroll
                for (int mt = 0; mt < 2; mt++) {
                    asm volatile(
                        "mma.sync.aligned.m16n8k8.row.col.f32.tf32.tf32.f32 "
                        "{%0,%1,%2,%3}, {%4,%5,%6,%7}, {%8,%9}, {%0,%1,%2,%3};\n"
                        : "+f"(acc[mt][nt][0]), "+f"(acc[mt][nt][1]),
                          "+f"(acc[mt][nt][2]), "+f"(acc[mt][nt][3])
                        : "r"(af[mt][0]), "r"(af[mt][1]), "r"(af[mt][2]), "r"(af[mt][3]),
                          "r"(b0), "r"(b1));
                }
            }
        }
        __syncthreads();
    }

    #pragma unroll
    for (int mt = 0; mt < 2; mt++) {
        #pragma unroll
        for (int nt = 0; nt < 8; nt++) {
            int row = m0 + wm * 32 + mt * 16 + lrow;
            int col = wn * 64 + nt * 8 + lcol * 2;
            float bcol0 = bias[col], bcol1 = bias[col + 1];
            if (row < Mm) {
                float2 v = {acc[mt][nt][0] + bcol0, acc[mt][nt][1] + bcol1};
                *(float2*)&h[(size_t)row * OUT + col] = v;
            }
            if (row + 8 < Mm) {
                float2 v = {acc[mt][nt][2] + bcol0, acc[mt][nt][3] + bcol1};
                *(float2*)&h[(size_t)(row + 8) * OUT + col] = v;
            }
        }
    }
}

// ---- K2: edge scoring + degree count. One warp per edge. ----
__global__ void k_score(const int* __restrict__ ei, const float* __restrict__ att) {
    int gid  = blockIdx.x * blockDim.x + threadIdx.x;
    int e    = gid >> 5;
    int lane = threadIdx.x & 31;
    if (e >= Ee) return;
    int s = ei[e], d = ei[Ee + e];
    const float4 l4 = *(const float4*)(g_hl + (size_t)s * OUT + lane * 4);
    const float4 r4 = *(const float4*)(g_hr + (size_t)d * OUT + lane * 4);
    const float4 a4 = *(const float4*)(att + lane * 4);
    float vx = l4.x + r4.x, vy = l4.y + r4.y, vz = l4.z + r4.z, vw = l4.w + r4.w;
    vx = vx > 0.f ? vx : NEG_SLOPE_GAT * vx;
    vy = vy > 0.f ? vy : NEG_SLOPE_GAT * vy;
    vz = vz > 0.f ? vz : NEG_SLOPE_GAT * vz;
    vw = vw > 0.f ? vw : NEG_SLOPE_GAT * vw;
    float p = vx * a4.x + vy * a4.y + vz * a4.z + vw * a4.w;
    #pragma unroll
    for (int off = 8; off > 0; off >>= 1)
        p += __shfl_xor_sync(0xFFFFFFFFu, p, off);
    float other = __shfl_sync(0xFFFFFFFFu, p, 16);
    if (lane == 0) {
        g_logits[e] = make_float2(p, other);
        atomicAdd(&g_deg[d], 1);
    }
}

// ---- K3a: per-block degree sums ----
__global__ void k_scan_a() {
    __shared__ int wsum[32];
    int t = threadIdx.x, b = blockIdx.x;
    int idx = b * SCAN_T + t;
    int v = (idx < Mm) ? g_deg[idx] : 0;
    int s = v;
    #pragma unroll
    for (int off = 16; off > 0; off >>= 1)
        s += __shfl_xor_sync(0xFFFFFFFFu, s, off);
    if ((t & 31) == 0) wsum[t >> 5] = s;
    __syncthreads();
    if (t < 32) {
        int ws = wsum[t];
        #pragma unroll
        for (int off = 16; off > 0; off >>= 1)
            ws += __shfl_xor_sync(0xFFFFFFFFu, ws, off);
        if (t == 0) g_blocksum[b] = ws;
    }
}

// ---- K3b: scan the 98 block sums (one small block) ----
__global__ void k_scan_b() {
    __shared__ int sh[128];
    int t = threadIdx.x;
    int v = (t < NSB) ? g_blocksum[t] : 0;
    sh[t] = v;
    __syncthreads();
    #pragma unroll
    for (int off = 1; off < 128; off <<= 1) {
        int x = (t >= off) ? sh[t - off] : 0;
        __syncthreads();
        sh[t] += x;
        __syncthreads();
    }
    if (t < NSB) g_blockoff[t] = sh[t] - v;   // exclusive
    if (t == 127) g_rowptr[Mm] = sh[127];
}

// ---- K3c: block-wide exclusive scan + offset -> rowptr ----
__global__ void k_scan_c() {
    __shared__ int wsum[32];
    int t = threadIdx.x, b = blockIdx.x;
    int idx  = b * SCAN_T + t;
    int lane = t & 31, w = t >> 5;
    int v = (idx < Mm) ? g_deg[idx] : 0;
    int s = v;
    #pragma unroll
    for (int off = 1; off < 32; off <<= 1) {
        int x = __shfl_up_sync(0xFFFFFFFFu, s, off);
        if (lane >= off) s += x;
    }
    if (lane == 31) wsum[w] = s;
    __syncthreads();
    if (t < 32) {
        int ws = wsum[t];
        #pragma unroll
        for (int off = 1; off < 32; off <<= 1) {
            int x = __shfl_up_sync(0xFFFFFFFFu, ws, off);
            if (t >= off) ws += x;
        }
        wsum[t] = ws;
    }
    __syncthreads();
    int woff = (w == 0) ? 0 : wsum[w - 1];
    if (idx < Mm) g_rowptr[idx] = (s - v) + woff + g_blockoff[b];
}

// ---- K4: scatter edges into CSR order ----
__global__ void k_scatter(const int* __restrict__ ei) {
    int e = blockIdx.x * blockDim.x + threadIdx.x;
    if (e >= Ee) return;
    int d = ei[Ee + e];
    int pos = g_rowptr[d] + atomicAdd(&g_cnt[d], 1);
    g_csr_src[pos]   = ei[e];
    g_csr_logit[pos] = g_logits[e];
}

// ---- K5: gather-aggregate + softmax + bias + LayerNorm + LeakyReLU. Warp per dst. ----
__global__ void __launch_bounds__(256)
k_gather(float* __restrict__ out, const float* __restrict__ bias,
         const float* __restrict__ gamma, const float* __restrict__ beta) {
    int gid  = blockIdx.x * blockDim.x + threadIdx.x;
    int m    = gid >> 5;
    int lane = threadIdx.x & 31;
    if (m >= Mm) return;
    int start = g_rowptr[m];
    int deg   = g_rowptr[m + 1] - start;

    float mx0 = -CUDART_INF_F, mx1 = -CUDART_INF_F;
    for (int j = lane; j < deg; j += 32) {
        float2 l = g_csr_logit[start + j];
        mx0 = fmaxf(mx0, l.x);
        mx1 = fmaxf(mx1, l.y);
    }
    #pragma unroll
    for (int off = 16; off > 0; off >>= 1) {
        mx0 = fmaxf(mx0, __shfl_xor_sync(0xFFFFFFFFu, mx0, off));
        mx1 = fmaxf(mx1, __shfl_xor_sync(0xFFFFFFFFu, mx1, off));
    }

    int   hh = lane >> 4;
    float acc0 = 0.f, acc1 = 0.f, acc2 = 0.f, acc3 = 0.f;
    float den0 = 0.f, den1 = 0.f;

    for (int j = 0; j < deg; j++) {
        float2 l = g_csr_logit[start + j];
        int    s = g_csr_src[start + j];
        float w0 = __expf(l.x - mx0);
        float w1 = __expf(l.y - mx1);
        den0 += w0; den1 += w1;
        float w = hh ? w1 : w0;
        const float4 v = *(const float4*)(g_hl + (size_t)s * OUT + lane * 4);
        acc0 += w * v.x; acc1 += w * v.y; acc2 += w * v.z; acc3 += w * v.w;
    }

    float inv_d = 1.f / ((hh ? den1 : den0) + SOFTMAX_EPS);
    const float4 b4 = *(const float4*)(bias + lane * 4);
    float v0 = acc0 * inv_d + b4.x;
    float v1 = acc1 * inv_d + b4.y;
    float v2 = acc2 * inv_d + b4.z;
    float v3 = acc3 * inv_d + b4.w;

    float s  = v0 + v1 + v2 + v3;
    float s2 = v0 * v0 + v1 * v1 + v2 * v2 + v3 * v3;
    #pragma unroll
    for (int off = 16; off > 0; off >>= 1) {
        s  += __shfl_xor_sync(0xFFFFFFFFu, s,  off);
        s2 += __shfl_xor_sync(0xFFFFFFFFu, s2, off);
    }
    float mu  = s * (1.f / OUT);
    float var = s2 * (1.f / OUT) - mu * mu;
    float inv = rsqrtf(var + LN_EPS);

    const float4 g4 = *(const float4*)(gamma + lane * 4);
    const float4 t4 = *(const float4*)(beta + lane * 4);
    float4 y;
    y.x = (v0 - mu) * inv * g4.x + t4.x;
    y.y = (v1 - mu) * inv * g4.y + t4.y;
    y.z = (v2 - mu) * inv * g4.z + t4.z;
    y.w = (v3 - mu) * inv * g4.w + t4.w;
    y.x = y.x > 0.f ? y.x : NEG_SLOPE_ACT * y.x;
    y.y = y.y > 0.f ? y.y : NEG_SLOPE_ACT * y.y;
    y.z = y.z > 0.f ? y.z : NEG_SLOPE_ACT * y.z;
    y.w = y.w > 0.f ? y.w : NEG_SLOPE_ACT * y.w;
    *(float4*)(out + (size_t)m * OUT + lane * 4) = y;
}

extern "C" void kernel_launch(void* const* d_in, const int* in_sizes, int n_in,
                              void* d_out, int out_size) {
    const float* x        = (const float*)d_in[0];
    const int*   ei       = (const int*)  d_in[1];
    const float* Wl       = (const float*)d_in[2];
    const float* bl       = (const float*)d_in[3];
    const float* Wr       = (const float*)d_in[4];
    const float* br       = (const float*)d_in[5];
    const float* att      = (const float*)d_in[6];
    const float* bias_gat = (const float*)d_in[7];
    const float* gamma    = (const float*)d_in[8];
    const float* beta     = (const float*)d_in[9];
    float* out = (float*)d_out;

    (void)in_sizes; (void)n_in; (void)out_size;

    k_init<<<(Mm + 255) / 256, 256>>>();

    dim3 ggrid((Mm + BM - 1) / BM, 2);
    k_gemm_tc<<<ggrid, 256>>>(x, Wl, bl, Wr, br);

    k_score<<<(Ee * 32 + 255) / 256, 256>>>(ei, att);
    k_scan_a<<<NSB, SCAN_T>>>();
    k_scan_b<<<1, 128>>>();
    k_scan_c<<<NSB, SCAN_T>>>();
    k_scatter<<<(Ee + 255) / 256, 256>>>(ei);
    k_gather<<<(Mm * 32 + 255) / 256, 256>>>(out, bias_gat, gamma, beta);
}

// round 5
// speedup vs baseline: 1.9135x; 1.4699x over previous
#include <cuda_runtime.h>
#include <cstdint>
#include <math_constants.h>

// Problem constants
constexpr int Bb  = 2;
constexpr int Cc  = 128;
constexpr int Nn  = 50000;
constexpr int Mm  = Bb * Nn;
constexpr int Hh  = 2;
constexpr int FHh = 64;
constexpr int OUT = Hh * FHh; // 128
constexpr int Ee  = 800000;

constexpr float NEG_SLOPE_GAT = 0.2f;
constexpr float NEG_SLOPE_ACT = 0.01f;
constexpr float LN_EPS = 1e-5f;
constexpr float SOFTMAX_EPS = 1e-16f;

// Parallel scan config
constexpr int SCAN_T  = 1024;
constexpr int NSB     = (Mm + SCAN_T - 1) / SCAN_T;  // 98 blocks

// Scratch (device globals: allocation-free)
__device__ float  g_hl[(size_t)Mm * OUT];
__device__ float  g_hr[(size_t)Mm * OUT];
__device__ int    g_deg[Mm];
__device__ int    g_cnt[Mm];
__device__ int    g_rowptr[Mm + 1];
__device__ int    g_csr_src[Ee];
__device__ int    g_blocksum[NSB];
__device__ int    g_blockoff[NSB];

__device__ __forceinline__ uint32_t f2tf32(float f) {
    uint32_t u;
    asm("cvt.rna.tf32.f32 %0, %1;" : "=r"(u) : "f"(f));
    return u;
}

// ---- K0: zero counters ----
__global__ void k_init() {
    int i = blockIdx.x * blockDim.x + threadIdx.x;
    if (i < Mm) { g_deg[i] = 0; g_cnt[i] = 0; }
}

// ---- K1: fused transpose + dual GEMM via tf32 mma.sync ----
constexpr int BM = 128, BN = 128, BK = 32;

__global__ void __launch_bounds__(256, 2)
k_gemm_tc(const float* __restrict__ x,
          const float* __restrict__ Wl, const float* __restrict__ bl,
          const float* __restrict__ Wr, const float* __restrict__ br) {
    const float* W    = blockIdx.y ? Wr : Wl;
    const float* bias = blockIdx.y ? br : bl;
    float* h          = blockIdx.y ? g_hr : g_hl;

    __shared__ uint32_t xs[BM][BK + 4];
    __shared__ uint32_t ws[BK][BN + 12];

    int tid  = threadIdx.x;
    int lane = tid & 31;
    int wid  = tid >> 5;
    int wm   = wid & 3;
    int wn   = wid >> 2;
    int lrow = lane >> 2;
    int lcol = lane & 3;

    int m0 = blockIdx.x * BM;

    int ml   = tid & 127;
    int kc   = tid >> 7;
    int m_l  = m0 + ml;
    bool rowok = m_l < Mm;
    int bb = rowok ? (m_l / Nn) : 0;
    int nn = rowok ? (m_l % Nn) : 0;
    const float* xrow = x + (size_t)bb * Cc * Nn + nn;

    float acc[2][8][4];
    #pragma unroll
    for (int mt = 0; mt < 2; mt++)
        #pragma unroll
        for (int nt = 0; nt < 8; nt++)
            #pragma unroll
            for (int q = 0; q < 4; q++) acc[mt][nt][q] = 0.f;

    for (int k0 = 0; k0 < Cc; k0 += BK) {
        #pragma unroll
        for (int k = kc; k < BK; k += 2) {
            float v = rowok ? xrow[(size_t)(k0 + k) * Nn] : 0.f;
            xs[ml][k] = f2tf32(v);
        }
        #pragma unroll
        for (int k = kc; k < BK; k += 2) {
            ws[k][ml] = f2tf32(W[(size_t)(k0 + k) * OUT + ml]);
        }
        __syncthreads();

        #pragma unroll
        for (int kk = 0; kk < 4; kk++) {
            int kb = kk * 8;
            uint32_t af[2][4];
            #pragma unroll
            for (int mt = 0; mt < 2; mt++) {
                int r = wm * 32 + mt * 16 + lrow;
                af[mt][0] = xs[r][kb + lcol];
                af[mt][1] = xs[r + 8][kb + lcol];
                af[mt][2] = xs[r][kb + lcol + 4];
                af[mt][3] = xs[r + 8][kb + lcol + 4];
            }
            #pragma unroll
            for (int nt = 0; nt < 8; nt++) {
                int cn = wn * 64 + nt * 8 + lrow;
                uint32_t b0 = ws[kb + lcol][cn];
                uint32_t b1 = ws[kb + lcol + 4][cn];
                #pragma unroll
                for (int mt = 0; mt < 2; mt++) {
                    asm volatile(
                        "mma.sync.aligned.m16n8k8.row.col.f32.tf32.tf32.f32 "
                        "{%0,%1,%2,%3}, {%4,%5,%6,%7}, {%8,%9}, {%0,%1,%2,%3};\n"
                        : "+f"(acc[mt][nt][0]), "+f"(acc[mt][nt][1]),
                          "+f"(acc[mt][nt][2]), "+f"(acc[mt][nt][3])
                        : "r"(af[mt][0]), "r"(af[mt][1]), "r"(af[mt][2]), "r"(af[mt][3]),
                          "r"(b0), "r"(b1));
                }
            }
        }
        __syncthreads();
    }

    #pragma unroll
    for (int mt = 0; mt < 2; mt++) {
        #pragma unroll
        for (int nt = 0; nt < 8; nt++) {
            int row = m0 + wm * 32 + mt * 16 + lrow;
            int col = wn * 64 + nt * 8 + lcol * 2;
            float bcol0 = bias[col], bcol1 = bias[col + 1];
            if (row < Mm) {
                float2 v = {acc[mt][nt][0] + bcol0, acc[mt][nt][1] + bcol1};
                *(float2*)&h[(size_t)row * OUT + col] = v;
            }
            if (row + 8 < Mm) {
                float2 v = {acc[mt][nt][2] + bcol0, acc[mt][nt][3] + bcol1};
                *(float2*)&h[(size_t)(row + 8) * OUT + col] = v;
            }
        }
    }
}

// ---- K2: degree count. One thread per edge. ----
__global__ void k_count(const int* __restrict__ ei) {
    int e = blockIdx.x * blockDim.x + threadIdx.x;
    if (e >= Ee) return;
    atomicAdd(&g_deg[ei[Ee + e]], 1);
}

// ---- K3a: per-block degree sums ----
__global__ void k_scan_a() {
    __shared__ int wsum[32];
    int t = threadIdx.x, b = blockIdx.x;
    int idx = b * SCAN_T + t;
    int v = (idx < Mm) ? g_deg[idx] : 0;
    int s = v;
    #pragma unroll
    for (int off = 16; off > 0; off >>= 1)
        s += __shfl_xor_sync(0xFFFFFFFFu, s, off);
    if ((t & 31) == 0) wsum[t >> 5] = s;
    __syncthreads();
    if (t < 32) {
        int ws = wsum[t];
        #pragma unroll
        for (int off = 16; off > 0; off >>= 1)
            ws += __shfl_xor_sync(0xFFFFFFFFu, ws, off);
        if (t == 0) g_blocksum[b] = ws;
    }
}

// ---- K3b: scan the block sums ----
__global__ void k_scan_b() {
    __shared__ int sh[128];
    int t = threadIdx.x;
    int v = (t < NSB) ? g_blocksum[t] : 0;
    sh[t] = v;
    __syncthreads();
    #pragma unroll
    for (int off = 1; off < 128; off <<= 1) {
        int x = (t >= off) ? sh[t - off] : 0;
        __syncthreads();
        sh[t] += x;
        __syncthreads();
    }
    if (t < NSB) g_blockoff[t] = sh[t] - v;   // exclusive
    if (t == 127) g_rowptr[Mm] = sh[127];
}

// ---- K3c: block-wide exclusive scan + offset -> rowptr ----
__global__ void k_scan_c() {
    __shared__ int wsum[32];
    int t = threadIdx.x, b = blockIdx.x;
    int idx  = b * SCAN_T + t;
    int lane = t & 31, w = t >> 5;
    int v = (idx < Mm) ? g_deg[idx] : 0;
    int s = v;
    #pragma unroll
    for (int off = 1; off < 32; off <<= 1) {
        int x = __shfl_up_sync(0xFFFFFFFFu, s, off);
        if (lane >= off) s += x;
    }
    if (lane == 31) wsum[w] = s;
    __syncthreads();
    if (t < 32) {
        int ws = wsum[t];
        #pragma unroll
        for (int off = 1; off < 32; off <<= 1) {
            int x = __shfl_up_sync(0xFFFFFFFFu, ws, off);
            if (t >= off) ws += x;
        }
        wsum[t] = ws;
    }
    __syncthreads();
    int woff = (w == 0) ? 0 : wsum[w - 1];
    if (idx < Mm) g_rowptr[idx] = (s - v) + woff + g_blockoff[b];
}

// ---- K4: scatter src indices into CSR order ----
__global__ void k_scatter(const int* __restrict__ ei) {
    int e = blockIdx.x * blockDim.x + threadIdx.x;
    if (e >= Ee) return;
    int d = ei[Ee + e];
    int pos = g_rowptr[d] + atomicAdd(&g_cnt[d], 1);
    g_csr_src[pos] = ei[e];
}

// ---- K5: fused scoring + online-softmax aggregation + bias + LN + LeakyReLU.
//      One warp per dst node. Lanes 0-15: head 0 (f 0..63), 16-31: head 1. ----
__global__ void __launch_bounds__(256)
k_gather(float* __restrict__ out, const float* __restrict__ att,
         const float* __restrict__ bias,
         const float* __restrict__ gamma, const float* __restrict__ beta) {
    int gid  = blockIdx.x * blockDim.x + threadIdx.x;
    int m    = gid >> 5;
    int lane = threadIdx.x & 31;
    if (m >= Mm) return;
    int start = g_rowptr[m];
    int deg   = g_rowptr[m + 1] - start;

    const float4 hr4 = *(const float4*)(g_hr + (size_t)m * OUT + lane * 4);
    const float4 a4  = *(const float4*)(att + lane * 4);

    float mh  = -CUDART_INF_F;   // running max for this lane's head
    float den = 0.f;
    float acc0 = 0.f, acc1 = 0.f, acc2 = 0.f, acc3 = 0.f;

    for (int j = 0; j < deg; j++) {
        int s = g_csr_src[start + j];                  // warp-broadcast load
        const float4 l4 = *(const float4*)(g_hl + (size_t)s * OUT + lane * 4);
        // GATv2 logit partial: att . leaky_relu(hl + hr)
        float ex = l4.x + hr4.x, ey = l4.y + hr4.y,
              ez = l4.z + hr4.z, ew = l4.w + hr4.w;
        ex = ex > 0.f ? ex : NEG_SLOPE_GAT * ex;
        ey = ey > 0.f ? ey : NEG_SLOPE_GAT * ey;
        ez = ez > 0.f ? ez : NEG_SLOPE_GAT * ez;
        ew = ew > 0.f ? ew : NEG_SLOPE_GAT * ew;
        float p = ex * a4.x + ey * a4.y + ez * a4.z + ew * a4.w;
        // reduce within the 16-lane half -> every lane holds its head's logit
        #pragma unroll
        for (int off = 8; off > 0; off >>= 1)
            p += __shfl_xor_sync(0xFFFFFFFFu, p, off);
        // online softmax update
        float mnew  = fmaxf(mh, p);
        float scale = __expf(mh - mnew);   // 0 when mh = -inf
        float w     = __expf(p  - mnew);
        den  = den * scale + w;
        acc0 = acc0 * scale + w * l4.x;
        acc1 = acc1 * scale + w * l4.y;
        acc2 = acc2 * scale + w * l4.z;
        acc3 = acc3 * scale + w * l4.w;
        mh = mnew;
    }

    float inv_d = 1.f / (den + SOFTMAX_EPS);
    const float4 b4 = *(const float4*)(bias + lane * 4);
    float v0 = acc0 * inv_d + b4.x;
    float v1 = acc1 * inv_d + b4.y;
    float v2 = acc2 * inv_d + b4.z;
    float v3 = acc3 * inv_d + b4.w;

    float s  = v0 + v1 + v2 + v3;
    float s2 = v0 * v0 + v1 * v1 + v2 * v2 + v3 * v3;
    #pragma unroll
    for (int off = 16; off > 0; off >>= 1) {
        s  += __shfl_xor_sync(0xFFFFFFFFu, s,  off);
        s2 += __shfl_xor_sync(0xFFFFFFFFu, s2, off);
    }
    float mu  = s * (1.f / OUT);
    float var = s2 * (1.f / OUT) - mu * mu;
    float inv = rsqrtf(var + LN_EPS);

    const float4 g4 = *(const float4*)(gamma + lane * 4);
    const float4 t4 = *(const float4*)(beta + lane * 4);
    float4 y;
    y.x = (v0 - mu) * inv * g4.x + t4.x;
    y.y = (v1 - mu) * inv * g4.y + t4.y;
    y.z = (v2 - mu) * inv * g4.z + t4.z;
    y.w = (v3 - mu) * inv * g4.w + t4.w;
    y.x = y.x > 0.f ? y.x : NEG_SLOPE_ACT * y.x;
    y.y = y.y > 0.f ? y.y : NEG_SLOPE_ACT * y.y;
    y.z = y.z > 0.f ? y.z : NEG_SLOPE_ACT * y.z;
    y.w = y.w > 0.f ? y.w : NEG_SLOPE_ACT * y.w;
    *(float4*)(out + (size_t)m * OUT + lane * 4) = y;
}

extern "C" void kernel_launch(void* const* d_in, const int* in_sizes, int n_in,
                              void* d_out, int out_size) {
    const float* x        = (const float*)d_in[0];
    const int*   ei       = (const int*)  d_in[1];
    const float* Wl       = (const float*)d_in[2];
    const float* bl       = (const float*)d_in[3];
    const float* Wr       = (const float*)d_in[4];
    const float* br       = (const float*)d_in[5];
    const float* att      = (const float*)d_in[6];
    const float* bias_gat = (const float*)d_in[7];
    const float* gamma    = (const float*)d_in[8];
    const float* beta     = (const float*)d_in[9];
    float* out = (float*)d_out;

    (void)in_sizes; (void)n_in; (void)out_size;

    k_init<<<(Mm + 255) / 256, 256>>>();
    k_count<<<(Ee + 255) / 256, 256>>>(ei);
    k_scan_a<<<NSB, SCAN_T>>>();
    k_scan_b<<<1, 128>>>();
    k_scan_c<<<NSB, SCAN_T>>>();
    k_scatter<<<(Ee + 255) / 256, 256>>>(ei);

    dim3 ggrid((Mm + BM - 1) / BM, 2);
    k_gemm_tc<<<ggrid, 256>>>(x, Wl, bl, Wr, br);

    k_gather<<<(Mm * 32 + 255) / 256, 256>>>(out, att, bias_gat, gamma, beta);
}